// round 1
// baseline (speedup 1.0000x reference)
#include <cuda_runtime.h>
#include <math.h>

// Problem constants
#define Sq   2048
#define Dm   512
#define NH   8
#define DKh  64
#define NB   2
#define FFd  2048
#define MROWS (NB*Sq)   // 4096

// ---------------- scratch (static device globals; no allocs) ----------------
__device__ float g_q  [MROWS*Dm];
__device__ float g_k  [MROWS*Dm];
__device__ float g_v  [MROWS*Dm];
__device__ float g_t0 [MROWS*Dm];
__device__ float g_o1 [MROWS*Dm];
__device__ float g_o2 [MROWS*Dm];
__device__ float g_ffh[MROWS*FFd];

// ---------------- generic NN GEMM: C = A[M,K] @ B[K,N] (+bias)(+relu) ------
// BM=128, BN=128, BK=8, TM=8, TN=8, 256 threads
template<bool RELU, bool BIAS>
__global__ void __launch_bounds__(256) gemm_nn(
    const float* __restrict__ A, const float* __restrict__ B,
    const float* __restrict__ bias, float* __restrict__ C,
    int M, int N, int K)
{
    __shared__ float As[8][129];
    __shared__ float Bs[8][128];

    const int t  = threadIdx.x;
    const int m0 = blockIdx.y * 128;
    const int n0 = blockIdx.x * 128;
    const int ty = t >> 4;       // 0..15
    const int tx = t & 15;       // 0..15

    float acc[8][8];
#pragma unroll
    for (int i = 0; i < 8; i++)
#pragma unroll
        for (int j = 0; j < 8; j++) acc[i][j] = 0.f;

    for (int k0 = 0; k0 < K; k0 += 8) {
        // load A tile 128x8, store transposed As[k][m]
        {
            int row = t >> 1, c4 = t & 1;
            float4 va = *(const float4*)&A[(size_t)(m0 + row) * K + k0 + c4 * 4];
            As[c4*4+0][row] = va.x; As[c4*4+1][row] = va.y;
            As[c4*4+2][row] = va.z; As[c4*4+3][row] = va.w;
        }
        // load B tile 8x128 direct Bs[k][n]
        {
            int row = t >> 5, c4 = t & 31;
            *(float4*)&Bs[row][c4*4] =
                *(const float4*)&B[(size_t)(k0 + row) * N + n0 + c4 * 4];
        }
        __syncthreads();
#pragma unroll
        for (int k = 0; k < 8; k++) {
            float ra[8], rb[8];
#pragma unroll
            for (int i = 0; i < 8; i++) ra[i] = As[k][ty*8 + i];
            float4 b0 = *(const float4*)&Bs[k][tx*8];
            float4 b1 = *(const float4*)&Bs[k][tx*8 + 4];
            rb[0]=b0.x; rb[1]=b0.y; rb[2]=b0.z; rb[3]=b0.w;
            rb[4]=b1.x; rb[5]=b1.y; rb[6]=b1.z; rb[7]=b1.w;
#pragma unroll
            for (int i = 0; i < 8; i++)
#pragma unroll
                for (int j = 0; j < 8; j++)
                    acc[i][j] = fmaf(ra[i], rb[j], acc[i][j]);
        }
        __syncthreads();
    }

#pragma unroll
    for (int i = 0; i < 8; i++) {
        size_t ro = (size_t)(m0 + ty*8 + i) * N + n0 + tx*8;
#pragma unroll
        for (int j = 0; j < 8; j += 4) {
            float4 v;
            v.x = acc[i][j+0]; v.y = acc[i][j+1];
            v.z = acc[i][j+2]; v.w = acc[i][j+3];
            if (BIAS) {
                const float4 vb = *(const float4*)&bias[n0 + tx*8 + j];
                v.x += vb.x; v.y += vb.y; v.z += vb.z; v.w += vb.w;
            }
            if (RELU) {
                v.x = fmaxf(v.x, 0.f); v.y = fmaxf(v.y, 0.f);
                v.z = fmaxf(v.z, 0.f); v.w = fmaxf(v.w, 0.f);
            }
            *(float4*)&C[ro + j] = v;
        }
    }
}

// ---------------- attention logits: out[bh,i,j] = scale*Q_i.K_j (+causal) ---
// BM=BN=128, K=64 (head dim), 256 threads, 8x8 per thread
__global__ void __launch_bounds__(256) attn_logits(
    const float* __restrict__ Q, const float* __restrict__ Km,
    float* __restrict__ out, int causal)
{
    const int bh = blockIdx.z;
    const int b  = bh >> 3, h = bh & 7;
    const int i0 = blockIdx.y * 128;
    const int j0 = blockIdx.x * 128;
    const int t  = threadIdx.x;
    float* Ob = out + (size_t)bh * Sq * Sq;

    if (causal && j0 > i0 + 127) {
        // fully masked tile: skip dot product entirely
        for (int idx = t; idx < 128*128; idx += 256) {
            int ii = idx >> 7, jj = idx & 127;
            Ob[(size_t)(i0 + ii) * Sq + j0 + jj] = -1e9f;
        }
        return;
    }

    const float* Qb = Q  + (size_t)b * Sq * Dm + h * DKh;
    const float* Kb = Km + (size_t)b * Sq * Dm + h * DKh;

    __shared__ float Qs[8][129];
    __shared__ float Ks[8][129];

    const int ty = t >> 4;
    const int tx = t & 15;
    float acc[8][8];
#pragma unroll
    for (int i = 0; i < 8; i++)
#pragma unroll
        for (int j = 0; j < 8; j++) acc[i][j] = 0.f;

    for (int k0 = 0; k0 < DKh; k0 += 8) {
        {
            int row = t >> 1, c4 = t & 1;
            float4 v = *(const float4*)&Qb[(size_t)(i0 + row) * Dm + k0 + c4*4];
            Qs[c4*4+0][row] = v.x; Qs[c4*4+1][row] = v.y;
            Qs[c4*4+2][row] = v.z; Qs[c4*4+3][row] = v.w;
        }
        {
            int row = t >> 1, c4 = t & 1;
            float4 v = *(const float4*)&Kb[(size_t)(j0 + row) * Dm + k0 + c4*4];
            Ks[c4*4+0][row] = v.x; Ks[c4*4+1][row] = v.y;
            Ks[c4*4+2][row] = v.z; Ks[c4*4+3][row] = v.w;
        }
        __syncthreads();
#pragma unroll
        for (int k = 0; k < 8; k++) {
            float ra[8], rb[8];
#pragma unroll
            for (int i = 0; i < 8; i++) ra[i] = Qs[k][ty*8 + i];
#pragma unroll
            for (int j = 0; j < 8; j++) rb[j] = Ks[k][tx*8 + j];
#pragma unroll
            for (int i = 0; i < 8; i++)
#pragma unroll
                for (int j = 0; j < 8; j++)
                    acc[i][j] = fmaf(ra[i], rb[j], acc[i][j]);
        }
        __syncthreads();
    }

    const float scale = 0.125f;  // 1/sqrt(64)
#pragma unroll
    for (int i = 0; i < 8; i++) {
        const int gi = i0 + ty*8 + i;
        size_t ro = (size_t)gi * Sq + j0 + tx*8;
#pragma unroll
        for (int j = 0; j < 8; j += 4) {
            float4 v;
            int gj = j0 + tx*8 + j;
            v.x = acc[i][j+0] * scale + ((causal && gj+0 > gi) ? -1e9f : 0.f);
            v.y = acc[i][j+1] * scale + ((causal && gj+1 > gi) ? -1e9f : 0.f);
            v.z = acc[i][j+2] * scale + ((causal && gj+2 > gi) ? -1e9f : 0.f);
            v.w = acc[i][j+3] * scale + ((causal && gj+3 > gi) ? -1e9f : 0.f);
            *(float4*)&Ob[ro + j] = v;
        }
    }
}

// ---------------- row softmax in-place, row length 2048 ---------------------
__global__ void __launch_bounds__(256) softmax_rows(float* __restrict__ aw)
{
    const size_t row = blockIdx.x;
    float* p = aw + row * Sq;
    const int t = threadIdx.x;
    __shared__ float red[8];

    float v[8];
#pragma unroll
    for (int i = 0; i < 8; i++) v[i] = p[t + i*256];

    float mx = v[0];
#pragma unroll
    for (int i = 1; i < 8; i++) mx = fmaxf(mx, v[i]);
#pragma unroll
    for (int o = 16; o; o >>= 1) mx = fmaxf(mx, __shfl_xor_sync(0xffffffffu, mx, o));
    if ((t & 31) == 0) red[t >> 5] = mx;
    __syncthreads();
    mx = red[0];
#pragma unroll
    for (int w = 1; w < 8; w++) mx = fmaxf(mx, red[w]);

    float sum = 0.f;
#pragma unroll
    for (int i = 0; i < 8; i++) { v[i] = __expf(v[i] - mx); sum += v[i]; }
#pragma unroll
    for (int o = 16; o; o >>= 1) sum += __shfl_xor_sync(0xffffffffu, sum, o);
    __syncthreads();
    if ((t & 31) == 0) red[t >> 5] = sum;
    __syncthreads();
    sum = red[0];
#pragma unroll
    for (int w = 1; w < 8; w++) sum += red[w];

    const float inv = 1.f / sum;
#pragma unroll
    for (int i = 0; i < 8; i++) p[t + i*256] = v[i] * inv;
}

// ---------------- AV: out[b,i,h*64+d] = sum_j aw[bh,i,j] * V[b,j,h*64+d] ----
// BM=128, BN=64, BK=8, TM=8, TN=4, 256 threads
__global__ void __launch_bounds__(256) attn_av(
    const float* __restrict__ aw, const float* __restrict__ V,
    float* __restrict__ out)
{
    const int bh = blockIdx.z;
    const int b  = bh >> 3, h = bh & 7;
    const int i0 = blockIdx.y * 128;
    const int t  = threadIdx.x;

    const float* Ab = aw  + (size_t)bh * Sq * Sq;
    const float* Bb = V   + (size_t)b * Sq * Dm + h * DKh;
    float*       Cb = out + (size_t)b * Sq * Dm + h * DKh;

    __shared__ float As[8][129];
    __shared__ float Bs[8][64];

    const int ty = t >> 4;
    const int tx = t & 15;
    float acc[8][4];
#pragma unroll
    for (int i = 0; i < 8; i++)
#pragma unroll
        for (int j = 0; j < 4; j++) acc[i][j] = 0.f;

    for (int k0 = 0; k0 < Sq; k0 += 8) {
        {
            int row = t >> 1, c4 = t & 1;
            float4 v = *(const float4*)&Ab[(size_t)(i0 + row) * Sq + k0 + c4*4];
            As[c4*4+0][row] = v.x; As[c4*4+1][row] = v.y;
            As[c4*4+2][row] = v.z; As[c4*4+3][row] = v.w;
        }
        if (t < 128) {
            int row = t >> 4, c4 = t & 15;
            *(float4*)&Bs[row][c4*4] =
                *(const float4*)&Bb[(size_t)(k0 + row) * Dm + c4*4];
        }
        __syncthreads();
#pragma unroll
        for (int k = 0; k < 8; k++) {
            float ra[8];
#pragma unroll
            for (int i = 0; i < 8; i++) ra[i] = As[k][ty*8 + i];
            float4 b0 = *(const float4*)&Bs[k][tx*4];
            float rb[4] = {b0.x, b0.y, b0.z, b0.w};
#pragma unroll
            for (int i = 0; i < 8; i++)
#pragma unroll
                for (int j = 0; j < 4; j++)
                    acc[i][j] = fmaf(ra[i], rb[j], acc[i][j]);
        }
        __syncthreads();
    }

#pragma unroll
    for (int i = 0; i < 8; i++) {
        float4 v; v.x = acc[i][0]; v.y = acc[i][1]; v.z = acc[i][2]; v.w = acc[i][3];
        *(float4*)&Cb[(size_t)(i0 + ty*8 + i) * Dm + tx*4] = v;
    }
}

// ---------------- residual add + layernorm over last dim (512) --------------
__global__ void __launch_bounds__(128) add_ln(
    const float* __restrict__ a, const float* __restrict__ r,
    const float* __restrict__ g, const float* __restrict__ be,
    float* __restrict__ out)
{
    const size_t row = blockIdx.x;
    const int t = threadIdx.x;  // 128 threads, 4 floats each
    __shared__ float red[4];

    float4 va = *(const float4*)&a[row * Dm + t*4];
    float4 vr = *(const float4*)&r[row * Dm + t*4];
    float x0 = va.x + vr.x, x1 = va.y + vr.y, x2 = va.z + vr.z, x3 = va.w + vr.w;

    float s = x0 + x1 + x2 + x3;
#pragma unroll
    for (int o = 16; o; o >>= 1) s += __shfl_xor_sync(0xffffffffu, s, o);
    if ((t & 31) == 0) red[t >> 5] = s;
    __syncthreads();
    float mean = (red[0] + red[1] + red[2] + red[3]) * (1.f / 512.f);

    float d0 = x0 - mean, d1 = x1 - mean, d2 = x2 - mean, d3 = x3 - mean;
    float vs = d0*d0 + d1*d1 + d2*d2 + d3*d3;
#pragma unroll
    for (int o = 16; o; o >>= 1) vs += __shfl_xor_sync(0xffffffffu, vs, o);
    __syncthreads();
    if ((t & 31) == 0) red[t >> 5] = vs;
    __syncthreads();
    float var = (red[0] + red[1] + red[2] + red[3]) * (1.f / 512.f);
    float rstd = rsqrtf(var + 1e-6f);

    float4 vg = *(const float4*)&g[t*4];
    float4 vb = *(const float4*)&be[t*4];
    float4 o4;
    o4.x = d0 * rstd * vg.x + vb.x;
    o4.y = d1 * rstd * vg.y + vb.y;
    o4.z = d2 * rstd * vg.z + vb.z;
    o4.w = d3 * rstd * vg.w + vb.w;
    *(float4*)&out[row * Dm + t*4] = o4;
}

// ---------------- launch ----------------------------------------------------
extern "C" void kernel_launch(void* const* d_in, const int* in_sizes, int n_in,
                              void* d_out, int out_size)
{
    const float* x    = (const float*)d_in[0];
    const float* enc  = (const float*)d_in[1];
    // d_in[2] = look_ahead_mask (causality applied analytically)
    const float* wq1 = (const float*)d_in[3],  *bq1 = (const float*)d_in[4];
    const float* wk1 = (const float*)d_in[5],  *bk1 = (const float*)d_in[6];
    const float* wv1 = (const float*)d_in[7],  *bv1 = (const float*)d_in[8];
    const float* wo1 = (const float*)d_in[9],  *bo1 = (const float*)d_in[10];
    const float* wq2 = (const float*)d_in[11], *bq2 = (const float*)d_in[12];
    const float* wk2 = (const float*)d_in[13], *bk2 = (const float*)d_in[14];
    const float* wv2 = (const float*)d_in[15], *bv2 = (const float*)d_in[16];
    const float* wo2 = (const float*)d_in[17], *bo2 = (const float*)d_in[18];
    const float* wf1 = (const float*)d_in[19], *bf1 = (const float*)d_in[20];
    const float* wf2 = (const float*)d_in[21], *bf2 = (const float*)d_in[22];
    const float* g1 = (const float*)d_in[23], *be1 = (const float*)d_in[24];
    const float* g2 = (const float*)d_in[25], *be2 = (const float*)d_in[26];
    const float* g3 = (const float*)d_in[27], *be3 = (const float*)d_in[28];

    float* out3 = (float*)d_out;
    float* aw1  = out3 + (size_t)NB * Sq * Dm;                  // + 2,097,152
    float* aw2  = aw1  + (size_t)NB * NH * Sq * Sq;             // + 67,108,864

    float *q, *k, *v, *t0, *o1, *o2, *ffh;
    cudaGetSymbolAddress((void**)&q,   g_q);
    cudaGetSymbolAddress((void**)&k,   g_k);
    cudaGetSymbolAddress((void**)&v,   g_v);
    cudaGetSymbolAddress((void**)&t0,  g_t0);
    cudaGetSymbolAddress((void**)&o1,  g_o1);
    cudaGetSymbolAddress((void**)&o2,  g_o2);
    cudaGetSymbolAddress((void**)&ffh, g_ffh);

    const dim3 gProj(Dm / 128, MROWS / 128);        // (4, 32)
    const dim3 gFF1(FFd / 128, MROWS / 128);        // (16, 32)
    const dim3 gLog(Sq / 128, Sq / 128, NB * NH);   // (16, 16, 16)
    const dim3 gAV(1, Sq / 128, NB * NH);           // (1, 16, 16)

    // ---- self attention ----
    gemm_nn<false, true><<<gProj, 256>>>(x, wq1, bq1, q, MROWS, Dm, Dm);
    gemm_nn<false, true><<<gProj, 256>>>(x, wk1, bk1, k, MROWS, Dm, Dm);
    gemm_nn<false, true><<<gProj, 256>>>(x, wv1, bv1, v, MROWS, Dm, Dm);
    attn_logits<<<gLog, 256>>>(q, k, aw1, 1);
    softmax_rows<<<NB * NH * Sq, 256>>>(aw1);
    attn_av<<<gAV, 256>>>(aw1, v, t0);
    gemm_nn<false, true><<<gProj, 256>>>(t0, wo1, bo1, q, MROWS, Dm, Dm);
    add_ln<<<MROWS, 128>>>(q, x, g1, be1, o1);

    // ---- cross attention ----
    gemm_nn<false, true><<<gProj, 256>>>(o1, wq2, bq2, q, MROWS, Dm, Dm);
    gemm_nn<false, true><<<gProj, 256>>>(enc, wk2, bk2, k, MROWS, Dm, Dm);
    gemm_nn<false, true><<<gProj, 256>>>(enc, wv2, bv2, v, MROWS, Dm, Dm);
    attn_logits<<<gLog, 256>>>(q, k, aw2, 0);
    softmax_rows<<<NB * NH * Sq, 256>>>(aw2);
    attn_av<<<gAV, 256>>>(aw2, v, t0);
    gemm_nn<false, true><<<gProj, 256>>>(t0, wo2, bo2, q, MROWS, Dm, Dm);
    add_ln<<<MROWS, 128>>>(q, o1, g2, be2, o2);

    // ---- FFN ----
    gemm_nn<true,  true><<<gFF1, 256>>>(o2, wf1, bf1, ffh, MROWS, FFd, Dm);
    gemm_nn<false, true><<<gProj, 256>>>(ffh, wf2, bf2, t0, MROWS, Dm, FFd);
    add_ln<<<MROWS, 128>>>(t0, o2, g3, be3, out3);
}